// round 9
// baseline (speedup 1.0000x reference)
#include <cuda_runtime.h>
#include <cfloat>

#define N_TOK    16384
#define KCODES   8192
#define DIMD     64
#define ENC_CH   512
#define DEC_CH   512
#define OUT_MAIN (16*512*32*32)   /* 8388608 */

// ---------------- device scratch (no allocs allowed) ----------------
__device__ float g_wint[ENC_CH*DIMD];    // [c][d]   transposed w_in
__device__ float g_woutt[DIMD*DEC_CH];   // [d][o]   transposed w_out
__device__ float g_et[DIMD*KCODES];      // [d][k]   transposed embedding
__device__ float g_cn[KCODES];           // ||e_k||^2
__device__ float g_zt[DIMD*N_TOK];       // [d][n]   encoder output
__device__ float g_dec[KCODES*DEC_CH];   // [k][o]   decoded codebook (w_out@e + b_out)
__device__ int   g_idx[N_TOK];

typedef unsigned long long u64;

__device__ __forceinline__ u64 pack2(float lo, float hi){
    u64 r; asm("mov.b64 %0, {%1, %2};" : "=l"(r) : "f"(lo), "f"(hi)); return r;
}
__device__ __forceinline__ void unpack2(u64 v, float &lo, float &hi){
    asm("mov.b64 {%0, %1}, %2;" : "=f"(lo), "=f"(hi) : "l"(v));
}
__device__ __forceinline__ void fma2(u64 &d, u64 a, u64 b){
    asm("fma.rn.f32x2 %0, %1, %2, %3;" : "=l"(d) : "l"(a), "l"(b), "l"(d));
}

// ---------------- prep: transposes + codebook norms (one kernel) ----------------
__global__ __launch_bounds__(256) void prep_kernel(
    const float* __restrict__ w_in, const float* __restrict__ w_out,
    const float* __restrict__ emb)
{
    int i = blockIdx.x * 256 + threadIdx.x;
    if (i < ENC_CH*DIMD) {                       // w_in_t [c][d]
        int c = i >> 6, d = i & 63;
        g_wint[i] = w_in[d*ENC_CH + c];
    } else if (i < ENC_CH*DIMD + DIMD*DEC_CH) {  // w_out_t [d][o]
        int j = i - ENC_CH*DIMD;
        int d = j >> 9, o = j & 511;
        g_woutt[j] = w_out[o*DIMD + d];
    } else if (i < ENC_CH*DIMD + DIMD*DEC_CH + DIMD*KCODES) {  // e_t [d][k]
        int j = i - (ENC_CH*DIMD + DIMD*DEC_CH);
        int d = j >> 13, k = j & 8191;
        g_et[j] = emb[k*DIMD + d];
    } else {                                      // ||e_k||^2
        int k = i - (ENC_CH*DIMD + DIMD*DEC_CH + DIMD*KCODES);
        if (k < KCODES) {
            float s = 0.f;
            #pragma unroll
            for (int d = 0; d < DIMD; d++) { float v = emb[k*DIMD + d]; s += v*v; }
            g_cn[k] = s;
        }
    }
}

// ---------------- encoder: z_t[d][n] = sum_c x[b][c][hw]*w_in[d][c] + b_in[d] ----
__global__ __launch_bounds__(256) void enc_kernel(
    const float* __restrict__ x, const float* __restrict__ b_in)
{
    __shared__ float xs[64][64];   // [c][t]
    __shared__ float ws[64][64];   // [c][d]
    int tid = threadIdx.x;
    int tx = tid & 15, ty = tid >> 4;      // tx: d-group of 4, ty: token-group of 4
    int n0 = blockIdx.x * 64;
    int b = n0 >> 10, hw0 = n0 & 1023;
    const float* xb = x + b*ENC_CH*1024 + hw0;

    float acc[4][4] = {};
    for (int c0 = 0; c0 < ENC_CH; c0 += 64) {
        for (int i = tid; i < 4096; i += 256) {
            int c = i >> 6, t = i & 63;
            xs[c][t] = xb[(c0 + c)*1024 + t];
            ws[c][t] = g_wint[(c0 + c)*64 + t];
        }
        __syncthreads();
        #pragma unroll 8
        for (int c = 0; c < 64; c++) {
            float4 a4 = *(const float4*)&xs[c][ty*4];
            float4 b4 = *(const float4*)&ws[c][tx*4];
            float a[4] = {a4.x,a4.y,a4.z,a4.w};
            float w[4] = {b4.x,b4.y,b4.z,b4.w};
            #pragma unroll
            for (int i2 = 0; i2 < 4; i2++)
                #pragma unroll
                for (int j = 0; j < 4; j++)
                    acc[i2][j] += a[i2]*w[j];
        }
        __syncthreads();
    }
    #pragma unroll
    for (int j = 0; j < 4; j++) {
        int d = tx*4 + j;
        float bb = b_in[d];
        #pragma unroll
        for (int i2 = 0; i2 < 4; i2++)
            g_zt[d*N_TOK + n0 + ty*4 + i2] = acc[i2][j] + bb;
    }
}

// ---------------- decode table: g_dec[k][o] = sum_d e[k][d]*w_out[o][d] + b_out[o]
__global__ __launch_bounds__(256) void dec_table_kernel(const float* __restrict__ b_out)
{
    __shared__ float es[64][64];    // [d][code] 16KB
    __shared__ float ws[64][128];   // [d][o]    32KB
    int tid = threadIdx.x;
    int tx = tid & 15, ty = tid >> 4;   // tx: o-group of 8, ty: code-group of 4
    int k0 = (blockIdx.x >> 2) * 64;
    int o0 = (blockIdx.x & 3) * 128;

    for (int i = tid; i < 4096; i += 256) {
        int d = i >> 6, c = i & 63;
        es[d][c] = g_et[d*KCODES + k0 + c];
    }
    for (int i = tid; i < 8192; i += 256) {
        int d = i >> 7, o = i & 127;
        ws[d][o] = g_woutt[d*DEC_CH + o0 + o];
    }
    __syncthreads();

    float acc[4][8] = {};
    #pragma unroll 8
    for (int d = 0; d < 64; d++) {
        float4 c4 = *(const float4*)&es[d][ty*4];
        float4 wa = *(const float4*)&ws[d][tx*8];
        float4 wb = *(const float4*)&ws[d][tx*8+4];
        float cv[4] = {c4.x,c4.y,c4.z,c4.w};
        float wv[8] = {wa.x,wa.y,wa.z,wa.w,wb.x,wb.y,wb.z,wb.w};
        #pragma unroll
        for (int i2 = 0; i2 < 4; i2++)
            #pragma unroll
            for (int j = 0; j < 8; j++)
                acc[i2][j] += cv[i2]*wv[j];
    }
    #pragma unroll
    for (int i2 = 0; i2 < 4; i2++) {
        int krow = k0 + ty*4 + i2;
        #pragma unroll
        for (int j = 0; j < 8; j++) {
            int o = o0 + tx*8 + j;
            g_dec[krow*DEC_CH + o] = acc[i2][j] + b_out[o];
        }
    }
}

// ---------------- distance + argmin (dominant kernel, double-buffered) --------
// Per block: 64 tokens vs all 8192 codes, 64-code chunks, 128 chunks.
// Pipeline per chunk: LDG prefetch(next) -> FMA(current) -> STS prefetch -> BAR.
// score_k = ||e_k||^2 - 2*z.e_k computed as -2*(dot - c/2) with packed f32x2 FMA.
#define DCHUNK  64
#define DNCH    (KCODES/DCHUNK)   /* 128 */
__global__ __launch_bounds__(256) void dist_kernel(float* __restrict__ idx_out)
{
    __shared__ float zs[64][64];        // [d][t]           16KB
    __shared__ u64   es[2][64][32];     // [buf][d][pair]   2 x 16KB
    int tid = threadIdx.x;
    int tx = tid & 15, ty = tid >> 4;   // tx: 2-pair group (4 codes), ty: token-group of 4
    int n0 = blockIdx.x * 64;

    for (int i = tid; i < 4096; i += 256) {
        int d = i >> 6, t = i & 63;
        zs[d][t] = g_zt[d*N_TOK + n0 + t];
    }
    // prefetch chunk 0 into buffer 0
    {
        int d0 = tid >> 5, p = tid & 31;
        #pragma unroll
        for (int j = 0; j < 8; j++)
            es[0][d0 + j*8][p] = *(const u64*)(g_et + (d0 + j*8)*KCODES + 2*p);
    }
    __syncthreads();

    float best[4] = {FLT_MAX, FLT_MAX, FLT_MAX, FLT_MAX};
    int   bidx[4] = {0,0,0,0};
    int d0 = tid >> 5, p0 = tid & 31;

    for (int nc = 0; nc < DNCH; nc++) {
        int cur = nc & 1;
        int c0 = nc * DCHUNK;

        // issue prefetch LDGs for next chunk early (latency hidden by FMA block)
        u64 r[8];
        if (nc + 1 < DNCH) {
            const float* src = g_et + (nc + 1)*DCHUNK + 2*p0;
            #pragma unroll
            for (int j = 0; j < 8; j++)
                r[j] = *(const u64*)(src + (d0 + j*8)*KCODES);
        }

        // accumulators init with -c/2 (shared across the 4 token rows)
        u64 acc[4][2];
        const float* cp = g_cn + c0 + tx*4;
        #pragma unroll
        for (int j = 0; j < 2; j++) {
            u64 cj = pack2(-0.5f*cp[2*j], -0.5f*cp[2*j+1]);
            acc[0][j] = cj; acc[1][j] = cj; acc[2][j] = cj; acc[3][j] = cj;
        }

        #pragma unroll 8
        for (int d = 0; d < 64; d++) {
            float4 z4 = *(const float4*)&zs[d][ty*4];
            ulonglong2 e2 = *(const ulonglong2*)&es[cur][d][tx*2];
            u64 za0 = pack2(z4.x, z4.x);
            u64 za1 = pack2(z4.y, z4.y);
            u64 za2 = pack2(z4.z, z4.z);
            u64 za3 = pack2(z4.w, z4.w);
            fma2(acc[0][0], za0, e2.x); fma2(acc[0][1], za0, e2.y);
            fma2(acc[1][0], za1, e2.x); fma2(acc[1][1], za1, e2.y);
            fma2(acc[2][0], za2, e2.x); fma2(acc[2][1], za2, e2.y);
            fma2(acc[3][0], za3, e2.x); fma2(acc[3][1], za3, e2.y);
        }

        // epilogue: score = -2*acc; per-thread codes ascending -> first-min kept
        #pragma unroll
        for (int i2 = 0; i2 < 4; i2++) {
            #pragma unroll
            for (int j = 0; j < 2; j++) {
                float lo, hi;
                unpack2(acc[i2][j], lo, hi);
                float slo = -2.0f*lo, shi = -2.0f*hi;
                int code = c0 + tx*4 + 2*j;
                if (slo < best[i2]) { best[i2] = slo; bidx[i2] = code; }
                if (shi < best[i2]) { best[i2] = shi; bidx[i2] = code + 1; }
            }
        }

        // land the prefetched tile, then one barrier
        if (nc + 1 < DNCH) {
            #pragma unroll
            for (int j = 0; j < 8; j++)
                es[cur ^ 1][d0 + j*8][p0] = r[j];
        }
        __syncthreads();
    }

    // reduce across tx (16 lanes per half-warp); tie -> lower index
    #pragma unroll
    for (int off = 1; off < 16; off <<= 1) {
        #pragma unroll
        for (int i2 = 0; i2 < 4; i2++) {
            float ov = __shfl_xor_sync(0xffffffffu, best[i2], off);
            int   oi = __shfl_xor_sync(0xffffffffu, bidx[i2], off);
            if (ov < best[i2] || (ov == best[i2] && oi < bidx[i2])) {
                best[i2] = ov; bidx[i2] = oi;
            }
        }
    }
    if (tx == 0) {
        #pragma unroll
        for (int i2 = 0; i2 < 4; i2++) {
            int n = n0 + ty*4 + i2;
            g_idx[n] = bidx[i2];
            if (idx_out) idx_out[n] = (float)bidx[i2];
        }
    }
}

// ---------------- scatter: out[b][o][hw] = g_dec[idx[n]][o] ----------------
__global__ __launch_bounds__(256) void scatter_kernel(float* __restrict__ out)
{
    __shared__ int   sidx[16];
    __shared__ float buf[16][513];
    int tid = threadIdx.x;
    int n0 = blockIdx.x * 16;
    int b = n0 >> 10, hw0 = n0 & 1023;
    if (tid < 16) sidx[tid] = g_idx[n0 + tid];
    __syncthreads();
    for (int i = tid; i < 16*512; i += 256) {
        int t = i >> 9, o = i & 511;
        buf[t][o] = g_dec[sidx[t]*DEC_CH + o];
    }
    __syncthreads();
    float* ob = out + b*DEC_CH*1024 + hw0;
    for (int i = tid; i < 16*512; i += 256) {
        int o = i >> 4, t = i & 15;
        ob[o*1024 + t] = buf[t][o];
    }
}

// ---------------- launch ----------------
extern "C" void kernel_launch(void* const* d_in, const int* in_sizes, int n_in,
                              void* d_out, int out_size)
{
    const float* x     = (const float*)d_in[0];
    const float* w_in  = (const float*)d_in[1];
    const float* b_in  = (const float*)d_in[2];
    const float* emb   = (const float*)d_in[3];
    const float* w_out = (const float*)d_in[4];
    const float* b_out = (const float*)d_in[5];
    float* out = (float*)d_out;
    float* idx_out = (out_size >= OUT_MAIN + N_TOK) ? (out + OUT_MAIN) : nullptr;

    int prep_items = ENC_CH*DIMD + DIMD*DEC_CH + DIMD*KCODES + KCODES;
    prep_kernel<<<(prep_items + 255)/256, 256>>>(w_in, w_out, emb);
    enc_kernel<<<N_TOK/64, 256>>>(x, b_in);
    dec_table_kernel<<<(KCODES/64)*(DEC_CH/128), 256>>>(b_out);
    dist_kernel<<<N_TOK/64, 256>>>(idx_out);
    scatter_kernel<<<N_TOK/16, 256>>>(out);
}

// round 12
// speedup vs baseline: 1.0204x; 1.0204x over previous
#include <cuda_runtime.h>
#include <cfloat>

#define N_TOK    16384
#define KCODES   8192
#define HALF_K   4096
#define DIMD     64
#define ENC_CH   512
#define DEC_CH   512
#define OUT_MAIN (16*512*32*32)   /* 8388608 */

// ---------------- device scratch (no allocs allowed) ----------------
__device__ float g_wint[ENC_CH*DIMD];    // [c][d]   transposed w_in
__device__ float g_woutt[DIMD*DEC_CH];   // [d][o]   transposed w_out
__device__ float g_et[DIMD*KCODES];      // [d][k]   transposed embedding
__device__ float g_cn[KCODES];           // ||e_k||^2
__device__ float g_zt[DIMD*N_TOK];       // [d][n]   encoder output
__device__ float g_dec[KCODES*DEC_CH];   // [k][o]   decoded codebook
__device__ float g_bs[2*N_TOK];          // per-half best score
__device__ int   g_bi[2*N_TOK];          // per-half best index

typedef unsigned long long u64;

__device__ __forceinline__ u64 pack2(float lo, float hi){
    u64 r; asm("mov.b64 %0, {%1, %2};" : "=l"(r) : "f"(lo), "f"(hi)); return r;
}
__device__ __forceinline__ void unpack2(u64 v, float &lo, float &hi){
    asm("mov.b64 {%0, %1}, %2;" : "=f"(lo), "=f"(hi) : "l"(v));
}
__device__ __forceinline__ void fma2(u64 &d, u64 a, u64 b){
    asm("fma.rn.f32x2 %0, %1, %2, %3;" : "=l"(d) : "l"(a), "l"(b), "l"(d));
}

// ---------------- prep: transposes + codebook norms ----------------
__global__ __launch_bounds__(256) void prep_kernel(
    const float* __restrict__ w_in, const float* __restrict__ w_out,
    const float* __restrict__ emb)
{
    int i = blockIdx.x * 256 + threadIdx.x;
    if (i < ENC_CH*DIMD) {
        int c = i >> 6, d = i & 63;
        g_wint[i] = w_in[d*ENC_CH + c];
    } else if (i < ENC_CH*DIMD + DIMD*DEC_CH) {
        int j = i - ENC_CH*DIMD;
        int d = j >> 9, o = j & 511;
        g_woutt[j] = w_out[o*DIMD + d];
    } else if (i < ENC_CH*DIMD + DIMD*DEC_CH + DIMD*KCODES) {
        int j = i - (ENC_CH*DIMD + DIMD*DEC_CH);
        int d = j >> 13, k = j & 8191;
        g_et[j] = emb[k*DIMD + d];
    } else {
        int k = i - (ENC_CH*DIMD + DIMD*DEC_CH + DIMD*KCODES);
        if (k < KCODES) {
            float s = 0.f;
            #pragma unroll
            for (int d = 0; d < DIMD; d++) { float v = emb[k*DIMD + d]; s += v*v; }
            g_cn[k] = s;
        }
    }
}

// ---------------- encoder ----------------
__global__ __launch_bounds__(256) void enc_kernel(
    const float* __restrict__ x, const float* __restrict__ b_in)
{
    __shared__ float xs[64][64];
    __shared__ float ws[64][64];
    int tid = threadIdx.x;
    int tx = tid & 15, ty = tid >> 4;
    int n0 = blockIdx.x * 64;
    int b = n0 >> 10, hw0 = n0 & 1023;
    const float* xb = x + b*ENC_CH*1024 + hw0;

    float acc[4][4] = {};
    for (int c0 = 0; c0 < ENC_CH; c0 += 64) {
        for (int i = tid; i < 4096; i += 256) {
            int c = i >> 6, t = i & 63;
            xs[c][t] = xb[(c0 + c)*1024 + t];
            ws[c][t] = g_wint[(c0 + c)*64 + t];
        }
        __syncthreads();
        #pragma unroll 8
        for (int c = 0; c < 64; c++) {
            float4 a4 = *(const float4*)&xs[c][ty*4];
            float4 b4 = *(const float4*)&ws[c][tx*4];
            float a[4] = {a4.x,a4.y,a4.z,a4.w};
            float w[4] = {b4.x,b4.y,b4.z,b4.w};
            #pragma unroll
            for (int i2 = 0; i2 < 4; i2++)
                #pragma unroll
                for (int j = 0; j < 4; j++)
                    acc[i2][j] += a[i2]*w[j];
        }
        __syncthreads();
    }
    #pragma unroll
    for (int j = 0; j < 4; j++) {
        int d = tx*4 + j;
        float bb = b_in[d];
        #pragma unroll
        for (int i2 = 0; i2 < 4; i2++)
            g_zt[d*N_TOK + n0 + ty*4 + i2] = acc[i2][j] + bb;
    }
}

// ---------------- decode table ----------------
__global__ __launch_bounds__(256) void dec_table_kernel(const float* __restrict__ b_out)
{
    __shared__ float es[64][64];
    __shared__ float ws[64][128];
    int tid = threadIdx.x;
    int tx = tid & 15, ty = tid >> 4;
    int k0 = (blockIdx.x >> 2) * 64;
    int o0 = (blockIdx.x & 3) * 128;

    for (int i = tid; i < 4096; i += 256) {
        int d = i >> 6, c = i & 63;
        es[d][c] = g_et[d*KCODES + k0 + c];
    }
    for (int i = tid; i < 8192; i += 256) {
        int d = i >> 7, o = i & 127;
        ws[d][o] = g_woutt[d*DEC_CH + o0 + o];
    }
    __syncthreads();

    float acc[4][8] = {};
    #pragma unroll 8
    for (int d = 0; d < 64; d++) {
        float4 c4 = *(const float4*)&es[d][ty*4];
        float4 wa = *(const float4*)&ws[d][tx*8];
        float4 wb = *(const float4*)&ws[d][tx*8+4];
        float cv[4] = {c4.x,c4.y,c4.z,c4.w};
        float wv[8] = {wa.x,wa.y,wa.z,wa.w,wb.x,wb.y,wb.z,wb.w};
        #pragma unroll
        for (int i2 = 0; i2 < 4; i2++)
            #pragma unroll
            for (int j = 0; j < 8; j++)
                acc[i2][j] += cv[i2]*wv[j];
    }
    #pragma unroll
    for (int i2 = 0; i2 < 4; i2++) {
        int krow = k0 + ty*4 + i2;
        #pragma unroll
        for (int j = 0; j < 8; j++) {
            int o = o0 + tx*8 + j;
            g_dec[krow*DEC_CH + o] = acc[i2][j] + b_out[o];
        }
    }
}

// ---------------- distance + argmin: split-K halves, wide-token warp tile ----
// Block (bid): tokens (bid>>1)*64, codebook half (bid&1)*4096.  512 blocks.
// Warp tile 16 tok x 32 codes: cx=lane&7 (code-quad), tg=lane>>3 (token-quad);
// tw=warp&3 (16-token slab), cw=warp>>2 (32-code half of 64-code chunk).
// Wavefronts per d-iter per warp: z 64B=1, e 128B=1  (was 3).
#define DCHUNK  64
#define DNCH    (HALF_K/DCHUNK)   /* 64 */
__global__ __launch_bounds__(256, 4) void dist_kernel()
{
    __shared__ float zs[64][64];        // [d][t]           16KB
    __shared__ u64   es[2][64][32];     // [buf][d][pair]   32KB  (total 48KB)
    int tid = threadIdx.x;
    int lane = tid & 31, w = tid >> 5;
    int cx = lane & 7, tg = lane >> 3;
    int tw = w & 3,   cw = w >> 2;
    int half  = blockIdx.x & 1;
    int n0    = (blockIdx.x >> 1) * 64;
    int cbase = half * HALF_K;

    for (int i = tid; i < 4096; i += 256) {
        int d = i >> 6, t = i & 63;
        zs[d][t] = g_zt[d*N_TOK + n0 + t];
    }
    int d0 = tid >> 5, p0 = tid & 31;
    #pragma unroll
    for (int j = 0; j < 8; j++)
        es[0][d0 + j*8][p0] = *(const u64*)(g_et + (d0 + j*8)*KCODES + cbase + 2*p0);
    __syncthreads();

    float best[4] = {FLT_MAX, FLT_MAX, FLT_MAX, FLT_MAX};
    int   bidx[4] = {0,0,0,0};
    int zcol = tw*16 + tg*4;       // token column for this thread
    int ecol = cw*16 + cx*2;       // pair column within chunk

    for (int nc = 0; nc < DNCH; nc++) {
        int cur = nc & 1;
        int c0 = cbase + nc * DCHUNK;

        u64 r[8];
        if (nc + 1 < DNCH) {
            const float* src = g_et + c0 + DCHUNK + 2*p0;
            #pragma unroll
            for (int j = 0; j < 8; j++)
                r[j] = *(const u64*)(src + (d0 + j*8)*KCODES);
        }

        u64 acc[4][2];
        const float* cp = g_cn + c0 + cw*32 + cx*4;
        #pragma unroll
        for (int j = 0; j < 2; j++) {
            u64 cj = pack2(-0.5f*cp[2*j], -0.5f*cp[2*j+1]);
            acc[0][j] = cj; acc[1][j] = cj; acc[2][j] = cj; acc[3][j] = cj;
        }

        #pragma unroll 8
        for (int d = 0; d < 64; d++) {
            float4 z4 = *(const float4*)&zs[d][zcol];
            ulonglong2 e2 = *(const ulonglong2*)&es[cur][d][ecol];
            u64 za0 = pack2(z4.x, z4.x);
            u64 za1 = pack2(z4.y, z4.y);
            u64 za2 = pack2(z4.z, z4.z);
            u64 za3 = pack2(z4.w, z4.w);
            fma2(acc[0][0], za0, e2.x); fma2(acc[0][1], za0, e2.y);
            fma2(acc[1][0], za1, e2.x); fma2(acc[1][1], za1, e2.y);
            fma2(acc[2][0], za2, e2.x); fma2(acc[2][1], za2, e2.y);
            fma2(acc[3][0], za3, e2.x); fma2(acc[3][1], za3, e2.y);
        }

        // score = -2*acc; per-thread codes ascending -> strict < keeps first-min
        #pragma unroll
        for (int i2 = 0; i2 < 4; i2++) {
            #pragma unroll
            for (int j = 0; j < 2; j++) {
                float lo, hi;
                unpack2(acc[i2][j], lo, hi);
                float slo = -2.0f*lo, shi = -2.0f*hi;
                int code = c0 + cw*32 + cx*4 + 2*j;
                if (slo < best[i2]) { best[i2] = slo; bidx[i2] = code; }
                if (shi < best[i2]) { best[i2] = shi; bidx[i2] = code + 1; }
            }
        }

        if (nc + 1 < DNCH) {
            #pragma unroll
            for (int j = 0; j < 8; j++)
                es[cur ^ 1][d0 + j*8][p0] = r[j];
        }
        __syncthreads();
    }

    // reduce over cx (8-lane groups); lexicographic (score, idx)
    #pragma unroll
    for (int off = 1; off < 8; off <<= 1) {
        #pragma unroll
        for (int i2 = 0; i2 < 4; i2++) {
            float ov = __shfl_xor_sync(0xffffffffu, best[i2], off);
            int   oi = __shfl_xor_sync(0xffffffffu, bidx[i2], off);
            if (ov < best[i2] || (ov == best[i2] && oi < bidx[i2])) {
                best[i2] = ov; bidx[i2] = oi;
            }
        }
    }

    // cross-warp merge (cw=1 -> cw=0) via smem scratch overlaid on dead es
    float* sbs = (float*)&es[0][0][0];
    int*   sbi = (int*)  &es[0][2][0];
    if (cw == 1 && cx == 0) {
        #pragma unroll
        for (int i2 = 0; i2 < 4; i2++) {
            sbs[tw*16 + tg*4 + i2] = best[i2];
            sbi[tw*16 + tg*4 + i2] = bidx[i2];
        }
    }
    __syncthreads();
    if (cw == 0 && cx == 0) {
        #pragma unroll
        for (int i2 = 0; i2 < 4; i2++) {
            int tl = tw*16 + tg*4 + i2;
            float s1 = sbs[tl]; int i1 = sbi[tl];
            if (s1 < best[i2] || (s1 == best[i2] && i1 < bidx[i2])) {
                best[i2] = s1; bidx[i2] = i1;
            }
            int n = n0 + tl;
            g_bs[half*N_TOK + n] = best[i2];
            g_bi[half*N_TOK + n] = bidx[i2];
        }
    }
}

// ---------------- scatter + half-merge: out[b][o][hw] = g_dec[argmin][o] ------
__global__ __launch_bounds__(256) void scatter_kernel(
    float* __restrict__ out, float* __restrict__ idx_out)
{
    __shared__ int   sidx[16];
    __shared__ float buf[16][513];
    int tid = threadIdx.x;
    int n0 = blockIdx.x * 16;
    int b = n0 >> 10, hw0 = n0 & 1023;
    if (tid < 16) {
        int n = n0 + tid;
        float s0 = g_bs[n], s1 = g_bs[N_TOK + n];
        // half-1 indices are all larger: strict < keeps first-min semantics
        int idx = (s1 < s0) ? g_bi[N_TOK + n] : g_bi[n];
        sidx[tid] = idx;
        if (idx_out) idx_out[n] = (float)idx;
    }
    __syncthreads();
    for (int i = tid; i < 16*512; i += 256) {
        int t = i >> 9, o = i & 511;
        buf[t][o] = g_dec[sidx[t]*DEC_CH + o];
    }
    __syncthreads();
    float* ob = out + b*DEC_CH*1024 + hw0;
    for (int i = tid; i < 16*512; i += 256) {
        int o = i >> 4, t = i & 15;
        ob[o*1024 + t] = buf[t][o];
    }
}

// ---------------- launch ----------------
extern "C" void kernel_launch(void* const* d_in, const int* in_sizes, int n_in,
                              void* d_out, int out_size)
{
    const float* x     = (const float*)d_in[0];
    const float* w_in  = (const float*)d_in[1];
    const float* b_in  = (const float*)d_in[2];
    const float* emb   = (const float*)d_in[3];
    const float* w_out = (const float*)d_in[4];
    const float* b_out = (const float*)d_in[5];
    float* out = (float*)d_out;
    float* idx_out = (out_size >= OUT_MAIN + N_TOK) ? (out + OUT_MAIN) : nullptr;

    int prep_items = ENC_CH*DIMD + DIMD*DEC_CH + DIMD*KCODES + KCODES;
    prep_kernel<<<(prep_items + 255)/256, 256>>>(w_in, w_out, emb);
    enc_kernel<<<N_TOK/64, 256>>>(x, b_in);
    dec_table_kernel<<<(KCODES/64)*(DEC_CH/128), 256>>>(b_out);
    dist_kernel<<<2*(N_TOK/64), 256>>>();
    scatter_kernel<<<N_TOK/16, 256>>>(out, idx_out);
}